// round 13
// baseline (speedup 1.0000x reference)
#include <cuda_runtime.h>
#include <cuda_bf16.h>
#include <cstdint>

// Problem dims (fixed by the dataset)
#define TT 512
#define NN 64
#define DD 1024
#define HH 1024
#define GG 4096        // 4*H

#define NBLK 128       // persistent blocks, 1/SM; block owns 8 hidden units

// recurrence smem layout (bytes):
//   whs_hi [32][1032] bf16   Wh^T slice (32 gate-cols, full K), pad 8
//   whs_lo [32][1032] bf16
//   ash    [2 bufs] { hi [64][136] bf16 ; lo [64][136] bf16 }   h chunk stage
//   pred   [64][34] f32  (aliases ash buf0, used post-MMA)
#define WSTB 1032
#define WHS_HI_OFF 0
#define WHS_LO_OFF (32 * WSTB * 2)            // 66048
#define ASH_OFF    (2 * 32 * WSTB * 2)        // 132096
#define ASH_HALF   (64 * 136 * 2)             // 17408
#define ASH_BUF    (2 * ASH_HALF)             // 34816
#define LSTM_SMEM  (ASH_OFF + 2 * ASH_BUF)    // 201728

// ---- device scratch (allocation-free per harness rules) ----
__device__ float g_xw[(size_t)TT * NN * GG];          // (T*N, 4H) x@Wx + b
__device__ __nv_bfloat16 g_hb_hi[2][NN * HH];         // h double-buffered, hi plane
__device__ __nv_bfloat16 g_hb_lo[2][NN * HH];         // lo plane
__device__ unsigned g_count;
__device__ unsigned g_gen;

// bf16 hi/lo split operands for the xW tensor GEMM (k-contiguous rows)
__device__ __nv_bfloat16 g_xa_hi[(size_t)TT * NN * DD];   // A[m][k], m = t*64+n
__device__ __nv_bfloat16 g_xa_lo[(size_t)TT * NN * DD];
__device__ __nv_bfloat16 g_wxt_hi[(size_t)GG * DD];       // B[g][k] = Wx[k][g]
__device__ __nv_bfloat16 g_wxt_lo[(size_t)GG * DD];

// ---------------------------------------------------------------------------
// helpers
// ---------------------------------------------------------------------------
__device__ __forceinline__ float sigm(float x) { return 1.f / (1.f + __expf(-x)); }
__device__ __forceinline__ float tanh_(float x) { return 2.f / (1.f + __expf(-2.f * x)) - 1.f; }

__device__ __forceinline__ void grid_sync() {
    __syncthreads();
    if (threadIdx.x == 0) {
        unsigned my;
        asm volatile("ld.acquire.gpu.global.u32 %0, [%1];" : "=r"(my) : "l"(&g_gen));
        __threadfence();
        if (atomicAdd(&g_count, 1) == NBLK - 1) {
            atomicExch(&g_count, 0);
            asm volatile("st.release.gpu.global.u32 [%0], %1;" :: "l"(&g_gen), "r"(my + 1));
        } else {
            unsigned cur;
            do {
                asm volatile("ld.acquire.gpu.global.u32 %0, [%1];" : "=r"(cur) : "l"(&g_gen));
            } while (cur == my);
        }
    }
    __syncthreads();
}

__device__ __forceinline__ uint32_t smem_u32(const void* p) {
    uint32_t a;
    asm("{ .reg .u64 t; cvta.to.shared.u64 t, %1; cvt.u32.u64 %0, t; }" : "=r"(a) : "l"(p));
    return a;
}

#define LDSM_X4(r0, r1, r2, r3, addr)                                           \
    asm volatile("ldmatrix.sync.aligned.m8n8.x4.shared.b16 {%0,%1,%2,%3}, [%4];" \
                 : "=r"(r0), "=r"(r1), "=r"(r2), "=r"(r3) : "r"(addr))

#define MMA_BF16(c, a0, a1, a2, a3, b0, b1)                                     \
    asm volatile("mma.sync.aligned.m16n8k16.row.col.f32.bf16.bf16.f32 "         \
                 "{%0,%1,%2,%3},{%4,%5,%6,%7},{%8,%9},{%0,%1,%2,%3};"           \
                 : "+f"(c[0]), "+f"(c[1]), "+f"(c[2]), "+f"(c[3])               \
                 : "r"(a0), "r"(a1), "r"(a2), "r"(a3), "r"(b0), "r"(b1))

// ---------------------------------------------------------------------------
// split kernels: fp32 -> bf16 hi + bf16 lo  (xW operands)
// ---------------------------------------------------------------------------
__global__ __launch_bounds__(256) void split_x(const float* __restrict__ x) {
    const int m = blockIdx.x;               // m = t*64 + n
    const int t = m >> 6, n = m & 63;
    const float* src = x + ((size_t)n * TT + t) * DD;
    const int d0 = threadIdx.x * 4;
    float4 v = *(const float4*)(src + d0);
    float f[4] = {v.x, v.y, v.z, v.w};
    ushort4 hi, lo;
    unsigned short* hp = &hi.x;
    unsigned short* lp = &lo.x;
    #pragma unroll
    for (int i = 0; i < 4; i++) {
        __nv_bfloat16 h = __float2bfloat16(f[i]);
        __nv_bfloat16 l = __float2bfloat16(f[i] - __bfloat162float(h));
        hp[i] = __bfloat16_as_ushort(h);
        lp[i] = __bfloat16_as_ushort(l);
    }
    size_t o = (size_t)m * DD + d0;
    *(ushort4*)&g_xa_hi[o] = hi;
    *(ushort4*)&g_xa_lo[o] = lo;
}

__global__ __launch_bounds__(256) void split_wx(const float* __restrict__ Wx) {
    __shared__ float tile[32][33];
    const int g0 = blockIdx.x * 32, k0 = blockIdx.y * 32;
    const int tx = threadIdx.x & 31, ty = threadIdx.x >> 5;   // 32 x 8
    #pragma unroll
    for (int j = 0; j < 4; j++)
        tile[ty + j * 8][tx] = Wx[(size_t)(k0 + ty + j * 8) * GG + g0 + tx];
    __syncthreads();
    #pragma unroll
    for (int j = 0; j < 4; j++) {
        float v = tile[tx][ty + j * 8];
        __nv_bfloat16 h = __float2bfloat16(v);
        __nv_bfloat16 l = __float2bfloat16(v - __bfloat162float(h));
        size_t o = (size_t)(g0 + ty + j * 8) * DD + k0 + tx;
        g_wxt_hi[o] = h;
        g_wxt_lo[o] = l;
    }
}

// ---------------------------------------------------------------------------
// xW GEMM on tensor cores (mma.sync bf16, 3-term hi/lo split). UNCHANGED (R7).
// ---------------------------------------------------------------------------
#define AST 40

__global__ __launch_bounds__(256) void xw_mma(const float* __restrict__ b) {
    __shared__ __nv_bfloat16 Ah[128 * AST], Al[128 * AST];
    __shared__ __nv_bfloat16 Bh[128 * AST], Bl[128 * AST];

    const int tid = threadIdx.x;
    const int wid = tid >> 5, lane = tid & 31;
    const int m0 = blockIdx.y * 128;
    const int g0 = blockIdx.x * 128;
    const int wm = (wid >> 2) * 64;
    const int wn = (wid & 3) * 32;

    float acc[4][4][4];
    #pragma unroll
    for (int i = 0; i < 4; i++)
        #pragma unroll
        for (int j = 0; j < 4; j++)
            #pragma unroll
            for (int q = 0; q < 4; q++) acc[i][j][q] = 0.f;

    const int sr = tid >> 1;
    const int sh = (tid & 1) * 16;

    const uint32_t ah_b = smem_u32(Ah), al_b = smem_u32(Al);
    const uint32_t bh_b = smem_u32(Bh), bl_b = smem_u32(Bl);
    const uint32_t a_off = (uint32_t)(wm + (lane & 15)) * (AST * 2) + ((lane >> 4) << 4);
    const uint32_t b_off = (uint32_t)(wn + ((lane >> 4) << 3) + (lane & 7)) * (AST * 2)
                           + (((lane >> 3) & 1) << 4);

    for (int k0 = 0; k0 < DD; k0 += 32) {
        {
            const size_t ga = (size_t)(m0 + sr) * DD + k0 + sh;
            const size_t gb = (size_t)(g0 + sr) * DD + k0 + sh;
            const int so = sr * AST + sh;
            *(uint4*)&Ah[so]     = *(const uint4*)&g_xa_hi[ga];
            *(uint4*)&Ah[so + 8] = *(const uint4*)&g_xa_hi[ga + 8];
            *(uint4*)&Al[so]     = *(const uint4*)&g_xa_lo[ga];
            *(uint4*)&Al[so + 8] = *(const uint4*)&g_xa_lo[ga + 8];
            *(uint4*)&Bh[so]     = *(const uint4*)&g_wxt_hi[gb];
            *(uint4*)&Bh[so + 8] = *(const uint4*)&g_wxt_hi[gb + 8];
            *(uint4*)&Bl[so]     = *(const uint4*)&g_wxt_lo[gb];
            *(uint4*)&Bl[so + 8] = *(const uint4*)&g_wxt_lo[gb + 8];
        }
        __syncthreads();

        #pragma unroll
        for (int ks = 0; ks < 32; ks += 16) {
            const uint32_t kb = (uint32_t)ks * 2;
            uint32_t bhf[4][2], blf[4][2];
            #pragma unroll
            for (int p = 0; p < 2; p++) {
                uint32_t r0, r1, r2, r3;
                uint32_t off = b_off + (uint32_t)(p * 16) * (AST * 2) + kb;
                LDSM_X4(r0, r1, r2, r3, bh_b + off);
                bhf[2 * p][0] = r0; bhf[2 * p][1] = r1;
                bhf[2 * p + 1][0] = r2; bhf[2 * p + 1][1] = r3;
                LDSM_X4(r0, r1, r2, r3, bl_b + off);
                blf[2 * p][0] = r0; blf[2 * p][1] = r1;
                blf[2 * p + 1][0] = r2; blf[2 * p + 1][1] = r3;
            }
            #pragma unroll
            for (int mt = 0; mt < 4; mt++) {
                uint32_t off = a_off + (uint32_t)(mt * 16) * (AST * 2) + kb;
                uint32_t ah0, ah1, ah2, ah3, al0, al1, al2, al3;
                LDSM_X4(ah0, ah1, ah2, ah3, ah_b + off);
                LDSM_X4(al0, al1, al2, al3, al_b + off);
                #pragma unroll
                for (int nt = 0; nt < 4; nt++) {
                    MMA_BF16(acc[mt][nt], ah0, ah1, ah2, ah3, bhf[nt][0], bhf[nt][1]);
                    MMA_BF16(acc[mt][nt], ah0, ah1, ah2, ah3, blf[nt][0], blf[nt][1]);
                    MMA_BF16(acc[mt][nt], al0, al1, al2, al3, bhf[nt][0], bhf[nt][1]);
                }
            }
        }
        __syncthreads();
    }

    const int er = lane >> 2;
    const int ec = (lane & 3) * 2;
    #pragma unroll
    for (int mt = 0; mt < 4; mt++) {
        #pragma unroll
        for (int nt = 0; nt < 4; nt++) {
            const int col = g0 + wn + (nt >> 1) * 16 + (nt & 1) * 8 + ec;
            const float2 bias = *(const float2*)&b[col];
            const int row = m0 + wm + mt * 16 + er;
            float2 v0 = make_float2(acc[mt][nt][0] + bias.x, acc[mt][nt][1] + bias.y);
            float2 v1 = make_float2(acc[mt][nt][2] + bias.x, acc[mt][nt][3] + bias.y);
            *(float2*)&g_xw[(size_t)row * GG + col] = v0;
            *(float2*)&g_xw[(size_t)(row + 8) * GG + col] = v1;
        }
    }
}

// ---------------------------------------------------------------------------
// Persistent LSTM recurrence: 128 blocks x 256 threads, 1 CTA/SM.
// Block owns 8 hidden units: computes all 4 gate columns (32 cols) over the
// FULL K=1024 -> gates fuse in-block, NO split-K partials, ONE grid_sync/step.
// Wh^T slice (32 cols, full K) SMEM-resident bf16 hi/lo.
// h double-buffered in GMEM as pre-split bf16 hi/lo planes; staged in 8
// chunks of K=128 through a double-buffered smem stage overlapped with MMA.
// Warp layout: 8 warps = 4(m:16 rows) x 2(n:16 cols).
// FIX vs R12: A-fragment address includes the warp row offset wm.
// ---------------------------------------------------------------------------
__global__ void __launch_bounds__(256, 1) lstm_persistent(
    const float* __restrict__ h0,
    const float* __restrict__ Wh,
    float* __restrict__ out) {
    extern __shared__ char smc[];
    const uint32_t sb = smem_u32(smc);
    __nv_bfloat16* whs_hi = (__nv_bfloat16*)(smc + WHS_HI_OFF);   // [32][WSTB]
    __nv_bfloat16* whs_lo = (__nv_bfloat16*)(smc + WHS_LO_OFF);
    float* pred = (float*)(smc + ASH_OFF);                        // [64][34]

    const int tid = threadIdx.x;
    const int blk = blockIdx.x;
    const int wid = tid >> 5, lane = tid & 31;
    const int j0 = blk * 8;            // hidden strip
    const int wm = (wid >> 1) * 16;    // warp row (batch) offset
    const int wn = (wid & 1) * 16;     // warp col offset (of 32)

    // ---- one-time: Wh^T slice -> smem bf16 hi/lo, [c][k] stride WSTB ----
    // c = 0..31 -> gate g = c>>3, hidden jj = c&7, gmem col = g*1024 + j0 + jj
    for (int idx = tid; idx < 32 * 1024; idx += 256) {
        const int cc = idx & 31;
        const int k = idx >> 5;
        const int gcol = (cc >> 3) * HH + j0 + (cc & 7);
        float v = Wh[(size_t)k * GG + gcol];
        __nv_bfloat16 h = __float2bfloat16(v);
        __nv_bfloat16 l = __float2bfloat16(v - __bfloat162float(h));
        whs_hi[cc * WSTB + k] = h;
        whs_lo[cc * WSTB + k] = l;
    }

    // ---- init h planes (buffer 0) from h0 ----
    {
        const int e = (blk * 256 + tid) * 2;
        float2 v = *(const float2*)&h0[e];
        __nv_bfloat16 h0a = __float2bfloat16(v.x);
        __nv_bfloat16 h0b = __float2bfloat16(v.y);
        __nv_bfloat16 l0a = __float2bfloat16(v.x - __bfloat162float(h0a));
        __nv_bfloat16 l0b = __float2bfloat16(v.y - __bfloat162float(h0b));
        *(uint32_t*)&g_hb_hi[0][e] =
            (uint32_t)__bfloat16_as_ushort(h0a) | ((uint32_t)__bfloat16_as_ushort(h0b) << 16);
        *(uint32_t*)&g_hb_lo[0][e] =
            (uint32_t)__bfloat16_as_ushort(l0a) | ((uint32_t)__bfloat16_as_ushort(l0b) << 16);
    }
    float2 c = make_float2(0.f, 0.f);
    grid_sync();

    // stage coords: row = tid>>2 (0..63), kq = (tid&3)*32 elements
    const int s_row = tid >> 2;
    const int s_kq = (tid & 3) * 32;

    // gate coords: cells (g_n, j0+g_jp), (g_n, j0+g_jp+1)
    const int g_n = tid & 63;
    const int g_jp = (tid >> 6) * 2;

    // ldmatrix offsets (bytes)  [FIX: wm included in A address]
    const uint32_t a_off = (uint32_t)(wm + (lane & 15)) * 272 + ((lane >> 4) << 4);
    const uint32_t b_off = (uint32_t)(wn + ((lane >> 4) << 3) + (lane & 7)) * (WSTB * 2)
                           + (((lane >> 3) & 1) << 4);
    const uint32_t bhi_s = sb + WHS_HI_OFF;
    const uint32_t blo_s = sb + WHS_LO_OFF;

    for (int t = 0; t < TT; ++t) {
        const int par = t & 1;
        const __nv_bfloat16* hbh = g_hb_hi[par];
        const __nv_bfloat16* hbl = g_hb_lo[par];

        // prefetch xw gate values for this thread's 2 cells
        float2 xg[4];
        {
            const float* xwt = g_xw + (size_t)t * NN * GG + (size_t)g_n * GG + j0 + g_jp;
            #pragma unroll
            for (int g = 0; g < 4; g++) xg[g] = *(const float2*)(xwt + g * HH);
        }

        // ---- stage chunk 0 ----
        {
            const int base = s_row * HH + s_kq;
            char* dh = smc + ASH_OFF + (s_row * 136 + s_kq) * 2;
            char* dl = dh + ASH_HALF;
            #pragma unroll
            for (int i = 0; i < 4; ++i) {
                *(uint4*)(dh + i * 16) = *(const uint4*)&hbh[base + i * 8];
                *(uint4*)(dl + i * 16) = *(const uint4*)&hbl[base + i * 8];
            }
        }
        __syncthreads();

        float accA[2][4], accB[2][4];
        #pragma unroll
        for (int nt = 0; nt < 2; nt++)
            #pragma unroll
            for (int q = 0; q < 4; q++) { accA[nt][q] = 0.f; accB[nt][q] = 0.f; }

        #pragma unroll 1
        for (int ch = 0; ch < 8; ++ch) {
            const int buf = ch & 1;
            // prefetch next chunk into registers (LDG latency covered by MMA)
            uint4 ph[4], pl[4];
            if (ch < 7) {
                const int base = s_row * HH + (ch + 1) * 128 + s_kq;
                #pragma unroll
                for (int i = 0; i < 4; ++i) {
                    ph[i] = *(const uint4*)&hbh[base + i * 8];
                    pl[i] = *(const uint4*)&hbl[base + i * 8];
                }
            }

            // MMA for chunk ch
            const uint32_t ah_s = sb + ASH_OFF + buf * ASH_BUF;
            const uint32_t al_s = ah_s + ASH_HALF;
            #pragma unroll
            for (int kk = 0; kk < 8; ++kk) {
                const uint32_t kba = (uint32_t)kk * 32;
                const uint32_t kbb = (uint32_t)(ch * 128 + kk * 16) * 2;
                uint32_t ah0, ah1, ah2, ah3, al0, al1, al2, al3;
                LDSM_X4(ah0, ah1, ah2, ah3, ah_s + a_off + kba);
                LDSM_X4(al0, al1, al2, al3, al_s + a_off + kba);
                uint32_t bh[2][2], bl[2][2];
                {
                    uint32_t r0, r1, r2, r3;
                    LDSM_X4(r0, r1, r2, r3, bhi_s + b_off + kbb);
                    bh[0][0] = r0; bh[0][1] = r1; bh[1][0] = r2; bh[1][1] = r3;
                    LDSM_X4(r0, r1, r2, r3, blo_s + b_off + kbb);
                    bl[0][0] = r0; bl[0][1] = r1; bl[1][0] = r2; bl[1][1] = r3;
                }
                #pragma unroll
                for (int nt = 0; nt < 2; nt++) {
                    MMA_BF16(accA[nt], ah0, ah1, ah2, ah3, bh[nt][0], bh[nt][1]);
                    MMA_BF16(accB[nt], ah0, ah1, ah2, ah3, bl[nt][0], bl[nt][1]);
                    MMA_BF16(accB[nt], al0, al1, al2, al3, bh[nt][0], bh[nt][1]);
                }
            }

            if (ch < 7) {
                char* dh = smc + ASH_OFF + (buf ^ 1) * ASH_BUF + (s_row * 136 + s_kq) * 2;
                char* dl = dh + ASH_HALF;
                #pragma unroll
                for (int i = 0; i < 4; ++i) {
                    *(uint4*)(dh + i * 16) = ph[i];
                    *(uint4*)(dl + i * 16) = pl[i];
                }
            }
            __syncthreads();
        }

        // ---- publish preacts to smem (pred aliases ash buf0; free now) ----
        {
            const int er = lane >> 2;
            const int ec = (lane & 3) * 2;
            #pragma unroll
            for (int nt = 0; nt < 2; nt++) {
                const int ccc = wn + nt * 8 + ec;
                *(float2*)&pred[(wm + er) * 34 + ccc] =
                    make_float2(accA[nt][0] + accB[nt][0], accA[nt][1] + accB[nt][1]);
                *(float2*)&pred[(wm + er + 8) * 34 + ccc] =
                    make_float2(accA[nt][2] + accB[nt][2], accA[nt][3] + accB[nt][3]);
            }
        }
        __syncthreads();

        // ---- gates: 2 cells per thread, c in registers ----
        {
            float2 pi = *(const float2*)&pred[g_n * 34 + 0 + g_jp];
            float2 pf = *(const float2*)&pred[g_n * 34 + 8 + g_jp];
            float2 po = *(const float2*)&pred[g_n * 34 + 16 + g_jp];
            float2 pg = *(const float2*)&pred[g_n * 34 + 24 + g_jp];
            pi.x += xg[0].x; pi.y += xg[0].y;
            pf.x += xg[1].x; pf.y += xg[1].y;
            po.x += xg[2].x; po.y += xg[2].y;
            pg.x += xg[3].x; pg.y += xg[3].y;

            float i0 = sigm(pi.x), f0 = sigm(pf.x), o0 = sigm(po.x), q0 = tanh_(pg.x);
            float i1 = sigm(pi.y), f1 = sigm(pf.y), o1 = sigm(po.y), q1 = tanh_(pg.y);
            c.x = f0 * c.x + i0 * q0;
            c.y = f1 * c.y + i1 * q1;
            float hv0 = o0 * tanh_(c.x);
            float hv1 = o1 * tanh_(c.y);

            // write h(t) as bf16 hi/lo planes into buffer par^1
            __nv_bfloat16 hh0 = __float2bfloat16(hv0);
            __nv_bfloat16 hh1 = __float2bfloat16(hv1);
            __nv_bfloat16 hl0 = __float2bfloat16(hv0 - __bfloat162float(hh0));
            __nv_bfloat16 hl1 = __float2bfloat16(hv1 - __bfloat162float(hh1));
            const int he = g_n * HH + j0 + g_jp;
            *(uint32_t*)&g_hb_hi[par ^ 1][he] =
                (uint32_t)__bfloat16_as_ushort(hh0) | ((uint32_t)__bfloat16_as_ushort(hh1) << 16);
            *(uint32_t*)&g_hb_lo[par ^ 1][he] =
                (uint32_t)__bfloat16_as_ushort(hl0) | ((uint32_t)__bfloat16_as_ushort(hl1) << 16);
            *(float2*)&out[((size_t)g_n * TT + t) * HH + j0 + g_jp] =
                make_float2(hv0, hv1);
        }
        grid_sync();   // h(t) published before any block stages step t+1
    }
}

// ---------------------------------------------------------------------------
// launch
// ---------------------------------------------------------------------------
extern "C" void kernel_launch(void* const* d_in, const int* in_sizes, int n_in,
                              void* d_out, int out_size) {
    const float* x  = (const float*)d_in[0];
    const float* h0 = (const float*)d_in[1];
    const float* Wx = (const float*)d_in[2];
    const float* Wh = (const float*)d_in[3];
    const float* b  = (const float*)d_in[4];
    float* out = (float*)d_out;

    cudaFuncSetAttribute(lstm_persistent, cudaFuncAttributeMaxDynamicSharedMemorySize, LSTM_SMEM);

    split_x<<<TT * NN, 256>>>(x);
    split_wx<<<dim3(GG / 32, DD / 32), 256>>>(Wx);
    xw_mma<<<dim3(GG / 128, (TT * NN) / 128), 256>>>(b);
    lstm_persistent<<<NBLK, 256, LSTM_SMEM>>>(h0, Wh, out);
}

// round 14
// speedup vs baseline: 1.3266x; 1.3266x over previous
#include <cuda_runtime.h>
#include <cuda_bf16.h>
#include <cstdint>

// Problem dims (fixed by the dataset)
#define TT 512
#define NN 64
#define DD 1024
#define HH 1024
#define GG 4096        // 4*H

#define NBLK 128       // persistent blocks, 1/SM
#define KS 8           // K splits for recurrent GEMM
#define KC (HH / KS)   // 128
#define CGRP 16        // column groups
#define CW (GG / CGRP) // 256 cols per group

// recurrence smem (bytes): Wh^T hi/lo [256][136] bf16 + h hi/lo [64][136] bf16
#define WST 136                         // k-stride (bf16 units) for ldmatrix
#define WHS_HI_OFF 0
#define WHS_LO_OFF (256 * WST * 2)                    // 69632
#define ASH_HI_OFF (2 * 256 * WST * 2)                // 139264
#define ASH_LO_OFF (ASH_HI_OFF + 64 * WST * 2)        // 156672
#define LSTM_SMEM  (ASH_LO_OFF + 64 * WST * 2)        // 174080

// ---- device scratch (allocation-free per harness rules) ----
__device__ float g_xw[(size_t)TT * NN * GG];        // (T*N, 4H) x@Wx + b
__device__ float g_part[KS][NN * GG];               // split-K partials of h@Wh
__device__ __nv_bfloat16 g_h_hi[NN * HH];           // hidden state, hi plane
__device__ __nv_bfloat16 g_h_lo[NN * HH];           // hidden state, lo plane
__device__ unsigned g_count;
__device__ unsigned g_gen;

// bf16 hi/lo split operands for the xW tensor GEMM (k-contiguous rows)
__device__ __nv_bfloat16 g_xa_hi[(size_t)TT * NN * DD];   // A[m][k], m = t*64+n
__device__ __nv_bfloat16 g_xa_lo[(size_t)TT * NN * DD];
__device__ __nv_bfloat16 g_wxt_hi[(size_t)GG * DD];       // B[g][k] = Wx[k][g]
__device__ __nv_bfloat16 g_wxt_lo[(size_t)GG * DD];

// ---------------------------------------------------------------------------
// helpers
// ---------------------------------------------------------------------------
__device__ __forceinline__ float sigm(float x) { return 1.f / (1.f + __expf(-x)); }
__device__ __forceinline__ float tanh_(float x) { return 2.f / (1.f + __expf(-2.f * x)) - 1.f; }

__device__ __forceinline__ void grid_sync() {
    __syncthreads();
    if (threadIdx.x == 0) {
        unsigned my;
        asm volatile("ld.acquire.gpu.global.u32 %0, [%1];" : "=r"(my) : "l"(&g_gen));
        __threadfence();
        if (atomicAdd(&g_count, 1) == NBLK - 1) {
            atomicExch(&g_count, 0);
            asm volatile("st.release.gpu.global.u32 [%0], %1;" :: "l"(&g_gen), "r"(my + 1));
        } else {
            unsigned cur;
            do {
                asm volatile("ld.acquire.gpu.global.u32 %0, [%1];" : "=r"(cur) : "l"(&g_gen));
            } while (cur == my);
        }
    }
    __syncthreads();
}

__device__ __forceinline__ uint32_t smem_u32(const void* p) {
    uint32_t a;
    asm("{ .reg .u64 t; cvta.to.shared.u64 t, %1; cvt.u32.u64 %0, t; }" : "=r"(a) : "l"(p));
    return a;
}

#define LDSM_X4(r0, r1, r2, r3, addr)                                           \
    asm volatile("ldmatrix.sync.aligned.m8n8.x4.shared.b16 {%0,%1,%2,%3}, [%4];" \
                 : "=r"(r0), "=r"(r1), "=r"(r2), "=r"(r3) : "r"(addr))

#define MMA_BF16(c, a0, a1, a2, a3, b0, b1)                                     \
    asm volatile("mma.sync.aligned.m16n8k16.row.col.f32.bf16.bf16.f32 "         \
                 "{%0,%1,%2,%3},{%4,%5,%6,%7},{%8,%9},{%0,%1,%2,%3};"           \
                 : "+f"(c[0]), "+f"(c[1]), "+f"(c[2]), "+f"(c[3])               \
                 : "r"(a0), "r"(a1), "r"(a2), "r"(a3), "r"(b0), "r"(b1))

// ---------------------------------------------------------------------------
// split kernels: fp32 -> bf16 hi + bf16 lo  (xW operands)
// ---------------------------------------------------------------------------
__global__ __launch_bounds__(256) void split_x(const float* __restrict__ x) {
    const int m = blockIdx.x;               // m = t*64 + n
    const int t = m >> 6, n = m & 63;
    const float* src = x + ((size_t)n * TT + t) * DD;
    const int d0 = threadIdx.x * 4;
    float4 v = *(const float4*)(src + d0);
    float f[4] = {v.x, v.y, v.z, v.w};
    ushort4 hi, lo;
    unsigned short* hp = &hi.x;
    unsigned short* lp = &lo.x;
    #pragma unroll
    for (int i = 0; i < 4; i++) {
        __nv_bfloat16 h = __float2bfloat16(f[i]);
        __nv_bfloat16 l = __float2bfloat16(f[i] - __bfloat162float(h));
        hp[i] = __bfloat16_as_ushort(h);
        lp[i] = __bfloat16_as_ushort(l);
    }
    size_t o = (size_t)m * DD + d0;
    *(ushort4*)&g_xa_hi[o] = hi;
    *(ushort4*)&g_xa_lo[o] = lo;
}

__global__ __launch_bounds__(256) void split_wx(const float* __restrict__ Wx) {
    __shared__ float tile[32][33];
    const int g0 = blockIdx.x * 32, k0 = blockIdx.y * 32;
    const int tx = threadIdx.x & 31, ty = threadIdx.x >> 5;   // 32 x 8
    #pragma unroll
    for (int j = 0; j < 4; j++)
        tile[ty + j * 8][tx] = Wx[(size_t)(k0 + ty + j * 8) * GG + g0 + tx];
    __syncthreads();
    #pragma unroll
    for (int j = 0; j < 4; j++) {
        float v = tile[tx][ty + j * 8];
        __nv_bfloat16 h = __float2bfloat16(v);
        __nv_bfloat16 l = __float2bfloat16(v - __bfloat162float(h));
        size_t o = (size_t)(g0 + ty + j * 8) * DD + k0 + tx;
        g_wxt_hi[o] = h;
        g_wxt_lo[o] = l;
    }
}

// ---------------------------------------------------------------------------
// xW GEMM on tensor cores (mma.sync bf16, 3-term hi/lo split). UNCHANGED (R7).
// ---------------------------------------------------------------------------
#define AST 40

__global__ __launch_bounds__(256) void xw_mma(const float* __restrict__ b) {
    __shared__ __nv_bfloat16 Ah[128 * AST], Al[128 * AST];
    __shared__ __nv_bfloat16 Bh[128 * AST], Bl[128 * AST];

    const int tid = threadIdx.x;
    const int wid = tid >> 5, lane = tid & 31;
    const int m0 = blockIdx.y * 128;
    const int g0 = blockIdx.x * 128;
    const int wm = (wid >> 2) * 64;
    const int wn = (wid & 3) * 32;

    float acc[4][4][4];
    #pragma unroll
    for (int i = 0; i < 4; i++)
        #pragma unroll
        for (int j = 0; j < 4; j++)
            #pragma unroll
            for (int q = 0; q < 4; q++) acc[i][j][q] = 0.f;

    const int sr = tid >> 1;
    const int sh = (tid & 1) * 16;

    const uint32_t ah_b = smem_u32(Ah), al_b = smem_u32(Al);
    const uint32_t bh_b = smem_u32(Bh), bl_b = smem_u32(Bl);
    const uint32_t a_off = (uint32_t)(wm + (lane & 15)) * (AST * 2) + ((lane >> 4) << 4);
    const uint32_t b_off = (uint32_t)(wn + ((lane >> 4) << 3) + (lane & 7)) * (AST * 2)
                           + (((lane >> 3) & 1) << 4);

    for (int k0 = 0; k0 < DD; k0 += 32) {
        {
            const size_t ga = (size_t)(m0 + sr) * DD + k0 + sh;
            const size_t gb = (size_t)(g0 + sr) * DD + k0 + sh;
            const int so = sr * AST + sh;
            *(uint4*)&Ah[so]     = *(const uint4*)&g_xa_hi[ga];
            *(uint4*)&Ah[so + 8] = *(const uint4*)&g_xa_hi[ga + 8];
            *(uint4*)&Al[so]     = *(const uint4*)&g_xa_lo[ga];
            *(uint4*)&Al[so + 8] = *(const uint4*)&g_xa_lo[ga + 8];
            *(uint4*)&Bh[so]     = *(const uint4*)&g_wxt_hi[gb];
            *(uint4*)&Bh[so + 8] = *(const uint4*)&g_wxt_hi[gb + 8];
            *(uint4*)&Bl[so]     = *(const uint4*)&g_wxt_lo[gb];
            *(uint4*)&Bl[so + 8] = *(const uint4*)&g_wxt_lo[gb + 8];
        }
        __syncthreads();

        #pragma unroll
        for (int ks = 0; ks < 32; ks += 16) {
            const uint32_t kb = (uint32_t)ks * 2;
            uint32_t bhf[4][2], blf[4][2];
            #pragma unroll
            for (int p = 0; p < 2; p++) {
                uint32_t r0, r1, r2, r3;
                uint32_t off = b_off + (uint32_t)(p * 16) * (AST * 2) + kb;
                LDSM_X4(r0, r1, r2, r3, bh_b + off);
                bhf[2 * p][0] = r0; bhf[2 * p][1] = r1;
                bhf[2 * p + 1][0] = r2; bhf[2 * p + 1][1] = r3;
                LDSM_X4(r0, r1, r2, r3, bl_b + off);
                blf[2 * p][0] = r0; blf[2 * p][1] = r1;
                blf[2 * p + 1][0] = r2; blf[2 * p + 1][1] = r3;
            }
            #pragma unroll
            for (int mt = 0; mt < 4; mt++) {
                uint32_t off = a_off + (uint32_t)(mt * 16) * (AST * 2) + kb;
                uint32_t ah0, ah1, ah2, ah3, al0, al1, al2, al3;
                LDSM_X4(ah0, ah1, ah2, ah3, ah_b + off);
                LDSM_X4(al0, al1, al2, al3, al_b + off);
                #pragma unroll
                for (int nt = 0; nt < 4; nt++) {
                    MMA_BF16(acc[mt][nt], ah0, ah1, ah2, ah3, bhf[nt][0], bhf[nt][1]);
                    MMA_BF16(acc[mt][nt], ah0, ah1, ah2, ah3, blf[nt][0], blf[nt][1]);
                    MMA_BF16(acc[mt][nt], al0, al1, al2, al3, bhf[nt][0], bhf[nt][1]);
                }
            }
        }
        __syncthreads();
    }

    const int er = lane >> 2;
    const int ec = (lane & 3) * 2;
    #pragma unroll
    for (int mt = 0; mt < 4; mt++) {
        #pragma unroll
        for (int nt = 0; nt < 4; nt++) {
            const int col = g0 + wn + (nt >> 1) * 16 + (nt & 1) * 8 + ec;
            const float2 bias = *(const float2*)&b[col];
            const int row = m0 + wm + mt * 16 + er;
            float2 v0 = make_float2(acc[mt][nt][0] + bias.x, acc[mt][nt][1] + bias.y);
            float2 v1 = make_float2(acc[mt][nt][2] + bias.x, acc[mt][nt][3] + bias.y);
            *(float2*)&g_xw[(size_t)row * GG + col] = v0;
            *(float2*)&g_xw[(size_t)(row + 8) * GG + col] = v1;
        }
    }
}

// ---------------------------------------------------------------------------
// Persistent LSTM recurrence (R10 design, h as bf16 hi/lo GMEM planes).
// 128 blocks x 256 threads, 1 CTA/SM. Split-K=8, col-groups=16.
// Wh^T slice SMEM-resident bf16 hi/lo [col][k] stride 136.
// Per step: stage h slice (pure 16KB+16KB copy), MMA (3-term split),
// store partials, grid_sync, gates (2 cells/thread, writes h planes),
// grid_sync.
// ---------------------------------------------------------------------------
__global__ void __launch_bounds__(256, 1) lstm_persistent(
    const float* __restrict__ h0,
    const float* __restrict__ Wh,
    float* __restrict__ out) {
    extern __shared__ char smc[];
    __nv_bfloat16* whs_hi = (__nv_bfloat16*)(smc + WHS_HI_OFF);   // [256][WST]
    __nv_bfloat16* whs_lo = (__nv_bfloat16*)(smc + WHS_LO_OFF);
    __nv_bfloat16* ash_hi = (__nv_bfloat16*)(smc + ASH_HI_OFF);   // [64][WST]
    __nv_bfloat16* ash_lo = (__nv_bfloat16*)(smc + ASH_LO_OFF);

    const int tid = threadIdx.x;
    const int blk = blockIdx.x;
    const int wid = tid >> 5, lane = tid & 31;
    const int cg = blk >> 3;           // 0..15 column group
    const int ks = blk & 7;            // 0..7  K split
    const int nc0 = cg * CW;
    const int kbase = ks * KC;
    const int wn = wid * 32;           // warp col offset (8 warps x 32 cols)

    // gate coords: 2 consecutive cells per thread
    const int ge = (blk * 256 + tid) * 2;
    const int gn = ge >> 10;
    const int gj = ge & 1023;

    // ---- one-time: Wh^T slice -> smem bf16 hi/lo, [col][k] stride WST ----
    for (int idx = tid; idx < CW * KC; idx += 256) {
        const int col = idx & 255;
        const int k = idx >> 8;
        float v = Wh[(size_t)(kbase + k) * GG + nc0 + col];
        __nv_bfloat16 h = __float2bfloat16(v);
        __nv_bfloat16 l = __float2bfloat16(v - __bfloat162float(h));
        whs_hi[col * WST + k] = h;
        whs_lo[col * WST + k] = l;
    }

    // ---- init h planes from h0 ----
    {
        float2 v = *(const float2*)&h0[ge];
        __nv_bfloat16 h0a = __float2bfloat16(v.x);
        __nv_bfloat16 h0b = __float2bfloat16(v.y);
        __nv_bfloat16 l0a = __float2bfloat16(v.x - __bfloat162float(h0a));
        __nv_bfloat16 l0b = __float2bfloat16(v.y - __bfloat162float(h0b));
        *(uint32_t*)&g_h_hi[ge] =
            (uint32_t)__bfloat16_as_ushort(h0a) | ((uint32_t)__bfloat16_as_ushort(h0b) << 16);
        *(uint32_t*)&g_h_lo[ge] =
            (uint32_t)__bfloat16_as_ushort(l0a) | ((uint32_t)__bfloat16_as_ushort(l0b) << 16);
    }
    float2 c = make_float2(0.f, 0.f);
    grid_sync();

    // stage coords: row = tid>>2 (0..63), kq = (tid&3)*32 elements
    const int s_row = tid >> 2;
    const int s_kq = (tid & 3) * 32;
    const __nv_bfloat16* hsrc_hi = g_h_hi + (size_t)s_row * HH + kbase + s_kq;
    const __nv_bfloat16* hsrc_lo = g_h_lo + (size_t)s_row * HH + kbase + s_kq;

    // ldmatrix offsets (bytes), stride WST*2 = 272
    const uint32_t ahi_b = smem_u32(ash_hi), alo_b = smem_u32(ash_lo);
    const uint32_t bhi_b = smem_u32(whs_hi), blo_b = smem_u32(whs_lo);
    const uint32_t a_off = (uint32_t)(lane & 15) * (WST * 2) + ((lane >> 4) << 4);
    const uint32_t b_off = (uint32_t)(wn + ((lane >> 4) << 3) + (lane & 7)) * (WST * 2)
                           + (((lane >> 3) & 1) << 4);

    for (int t = 0; t < TT; ++t) {
        // prefetch xw gate values (hidden behind MMA phase)
        float2 xg[4];
        {
            const float* xwt = g_xw + (size_t)t * NN * GG + (size_t)gn * GG + gj;
            #pragma unroll
            for (int g = 0; g < 4; g++) xg[g] = *(const float2*)(xwt + g * HH);
        }

        // ---------- stage: h slice -> smem (pure copy, no conversion) ----------
        {
            __nv_bfloat16* dh = ash_hi + s_row * WST + s_kq;
            __nv_bfloat16* dl = ash_lo + s_row * WST + s_kq;
            #pragma unroll
            for (int i = 0; i < 4; ++i) {
                *(uint4*)(dh + i * 8) = *(const uint4*)(hsrc_hi + i * 8);
                *(uint4*)(dl + i * 8) = *(const uint4*)(hsrc_lo + i * 8);
            }
        }
        __syncthreads();

        // ---------- MMA phase: 64 x 32(warp) x 128, 3-term split ----------
        float acc[4][4][4];
        #pragma unroll
        for (int i = 0; i < 4; i++)
            #pragma unroll
            for (int j = 0; j < 4; j++)
                #pragma unroll
                for (int q = 0; q < 4; q++) acc[i][j][q] = 0.f;

        #pragma unroll
        for (int kk = 0; kk < 8; ++kk) {
            const uint32_t kb = (uint32_t)kk * 32;   // 16 bf16 = 32 bytes
            uint32_t bhf[4][2], blf[4][2];
            #pragma unroll
            for (int p = 0; p < 2; p++) {
                uint32_t r0, r1, r2, r3;
                uint32_t off = b_off + (uint32_t)(p * 16) * (WST * 2) + kb;
                LDSM_X4(r0, r1, r2, r3, bhi_b + off);
                bhf[2 * p][0] = r0; bhf[2 * p][1] = r1;
                bhf[2 * p + 1][0] = r2; bhf[2 * p + 1][1] = r3;
                LDSM_X4(r0, r1, r2, r3, blo_b + off);
                blf[2 * p][0] = r0; blf[2 * p][1] = r1;
                blf[2 * p + 1][0] = r2; blf[2 * p + 1][1] = r3;
            }
            #pragma unroll
            for (int mt = 0; mt < 4; mt++) {
                uint32_t off = a_off + (uint32_t)(mt * 16) * (WST * 2) + kb;
                uint32_t ah0, ah1, ah2, ah3, al0, al1, al2, al3;
                LDSM_X4(ah0, ah1, ah2, ah3, ahi_b + off);
                LDSM_X4(al0, al1, al2, al3, alo_b + off);
                #pragma unroll
                for (int nt = 0; nt < 4; nt++) {
                    MMA_BF16(acc[mt][nt], ah0, ah1, ah2, ah3, bhf[nt][0], bhf[nt][1]);
                    MMA_BF16(acc[mt][nt], ah0, ah1, ah2, ah3, blf[nt][0], blf[nt][1]);
                    MMA_BF16(acc[mt][nt], al0, al1, al2, al3, bhf[nt][0], bhf[nt][1]);
                }
            }
        }
        __syncthreads();   // ash reuse next step

        // ---------- store partial tile (xw_mma epilogue mapping) ----------
        {
            float* dst = g_part[ks];
            const int er = lane >> 2;
            const int ec = (lane & 3) * 2;
            #pragma unroll
            for (int mt = 0; mt < 4; mt++) {
                #pragma unroll
                for (int nt = 0; nt < 4; nt++) {
                    const int col = nc0 + wn + (nt >> 1) * 16 + (nt & 1) * 8 + ec;
                    const int row = mt * 16 + er;
                    *(float2*)&dst[(size_t)row * GG + col] =
                        make_float2(acc[mt][nt][0], acc[mt][nt][1]);
                    *(float2*)&dst[(size_t)(row + 8) * GG + col] =
                        make_float2(acc[mt][nt][2], acc[mt][nt][3]);
                }
            }
        }
        grid_sync();

        // ---------- gates: 2 cells per thread ----------
        {
            size_t bi = (size_t)gn * GG + gj;
            float2 pi = xg[0], pf = xg[1], po = xg[2], pg = xg[3];
            #pragma unroll
            for (int s = 0; s < KS; ++s) {
                const float* p = g_part[s];
                float2 v;
                v = *(const float2*)&p[bi];          pi.x += v.x; pi.y += v.y;
                v = *(const float2*)&p[bi + HH];     pf.x += v.x; pf.y += v.y;
                v = *(const float2*)&p[bi + 2 * HH]; po.x += v.x; po.y += v.y;
                v = *(const float2*)&p[bi + 3 * HH]; pg.x += v.x; pg.y += v.y;
            }
            float i0 = sigm(pi.x), f0 = sigm(pf.x), o0 = sigm(po.x), q0 = tanh_(pg.x);
            float i1 = sigm(pi.y), f1 = sigm(pf.y), o1 = sigm(po.y), q1 = tanh_(pg.y);
            c.x = f0 * c.x + i0 * q0;
            c.y = f1 * c.y + i1 * q1;
            float hv0 = o0 * tanh_(c.x);
            float hv1 = o1 * tanh_(c.y);

            // write h(t) as bf16 hi/lo planes
            __nv_bfloat16 hh0 = __float2bfloat16(hv0);
            __nv_bfloat16 hh1 = __float2bfloat16(hv1);
            __nv_bfloat16 hl0 = __float2bfloat16(hv0 - __bfloat162float(hh0));
            __nv_bfloat16 hl1 = __float2bfloat16(hv1 - __bfloat162float(hh1));
            *(uint32_t*)&g_h_hi[ge] =
                (uint32_t)__bfloat16_as_ushort(hh0) | ((uint32_t)__bfloat16_as_ushort(hh1) << 16);
            *(uint32_t*)&g_h_lo[ge] =
                (uint32_t)__bfloat16_as_ushort(hl0) | ((uint32_t)__bfloat16_as_ushort(hl1) << 16);
            *(float2*)&out[((size_t)gn * TT + t) * HH + gj] = make_float2(hv0, hv1);
        }
        grid_sync();
    }
}

// ---------------------------------------------------------------------------
// launch
// ---------------------------------------------------------------------------
extern "C" void kernel_launch(void* const* d_in, const int* in_sizes, int n_in,
                              void* d_out, int out_size) {
    const float* x  = (const float*)d_in[0];
    const float* h0 = (const float*)d_in[1];
    const float* Wx = (const float*)d_in[2];
    const float* Wh = (const float*)d_in[3];
    const float* b  = (const float*)d_in[4];
    float* out = (float*)d_out;

    cudaFuncSetAttribute(lstm_persistent, cudaFuncAttributeMaxDynamicSharedMemorySize, LSTM_SMEM);

    split_x<<<TT * NN, 256>>>(x);
    split_wx<<<dim3(GG / 32, DD / 32), 256>>>(Wx);
    xw_mma<<<dim3(GG / 128, (TT * NN) / 128), 256>>>(b);
    lstm_persistent<<<NBLK, 256, LSTM_SMEM>>>(h0, Wh, out);
}